// round 1
// baseline (speedup 1.0000x reference)
#include <cuda_runtime.h>
#include <math.h>

// ---------------- problem constants ----------------
#define NB    8      // batch
#define BCAP  32     // B_ input capsules
#define NC    32     // C_ output capsules
#define WIN   14
#define WOUT  6
#define WW    36     // WOUT*WOUT
#define BKK   288    // K*K*B_
#define CWW   1152   // C_*WOUT*WOUT
#define EPSV  1e-10f
#define HALF_LN2PI 0.91893853320467274178f

// ---------------- device scratch (static: allocation-free) ----------------
__device__ float g_votes[(size_t)NB * CWW * BKK * 16];   // 162 MB, layout [b][cww][i][h]
__device__ float g_ap[(size_t)NB * CWW * BKK];           // R numerators, layout [b][cww][i]
__device__ float g_part[NB * 32 * BKK];                  // partial denom sums
__device__ float g_denom[NB * BKK];                      // denom[b][i]

__device__ __forceinline__ float4 rowmul(float4 wr, float4 p0, float4 p1, float4 p2, float4 p3) {
    float4 r;
    r.x = wr.x*p0.x + wr.y*p1.x + wr.z*p2.x + wr.w*p3.x;
    r.y = wr.x*p0.y + wr.y*p1.y + wr.z*p2.y + wr.w*p3.y;
    r.z = wr.x*p0.z + wr.y*p1.z + wr.z*p2.z + wr.w*p3.z;
    r.w = wr.x*p0.w + wr.y*p1.w + wr.z*p2.w + wr.w*p3.w;
    return r;
}

// One block per output column (b, cww). 288 threads = 16 h-lanes x 18 g-groups.
// Thread (g,h) owns V[i, h] for i = g + 18k, k=0..15 -> global offset tid + 288k (coalesced).
// PHASE 0: compute votes (write to g_votes), EM iter 0 (R = 1/C implicit), write ap.
// PHASE 1: read votes, R from ap/denom, EM iter, write ap (in-place safe: column-local).
// PHASE 2: read votes, R from ap/denom, final EM iter, write mu + a to d_out.
template <int PHASE>
__global__ __launch_bounds__(BKK)
void em_kernel(const float* __restrict__ poses, const float* __restrict__ act,
               const float* __restrict__ Wt, const float* __restrict__ beta_v,
               const float* __restrict__ beta_a, const float* __restrict__ lam,
               float* __restrict__ out)
{
    const int cww = blockIdx.x;
    const int b   = blockIdx.y;
    const int c   = cww / WW;
    const int s   = cww - c * WW;
    const int yw  = s / WOUT;
    const int xw  = s - yw * WOUT;
    const int t   = threadIdx.x;
    const int g   = t >> 4;        // 0..17
    const int h   = t & 15;        // 0..15
    const size_t colbase = (size_t)(b * CWW + cww) * BKK;

    __shared__ float Rw[BKK];
    __shared__ float red[BKK];
    __shared__ float red2[18];
    __shared__ float mu_s[16], logsig_s[16], inv2s_s[16];
    __shared__ float sumR_s, a_s;

    float Vr[16];

    if (PHASE == 0) {
        // ---- compute votes: thread t == input-capsule index i; V_i = W_i @ P_i (4x4) ----
        __shared__ __align__(16) float Vs[BKK * 16];
        const int i  = t;
        const int Bc = i / 9, uv = i - Bc * 9, u = uv / 3, v = uv - u * 3;
        const float4* Pp = reinterpret_cast<const float4*>(
            poses + ((size_t)((b * BCAP + Bc) * WIN + (2 * xw + u)) * WIN + (2 * yw + v)) * 16);
        const float4* Wp = reinterpret_cast<const float4*>(
            Wt + (size_t)(((Bc * 3 + u) * 3 + v) * NC + c) * 16);
        float4 p0 = Pp[0], p1 = Pp[1], p2 = Pp[2], p3 = Pp[3];
        float4 w0 = Wp[0], w1 = Wp[1], w2 = Wp[2], w3 = Wp[3];
        float4 r0 = rowmul(w0, p0, p1, p2, p3);
        float4 r1 = rowmul(w1, p0, p1, p2, p3);
        float4 r2 = rowmul(w2, p0, p1, p2, p3);
        float4 r3 = rowmul(w3, p0, p1, p2, p3);
        float4* vsl = reinterpret_cast<float4*>(Vs + i * 16);
        vsl[0] = r0; vsl[1] = r1; vsl[2] = r2; vsl[3] = r3;
        float4* vgl = reinterpret_cast<float4*>(g_votes + colbase * 16 + (size_t)i * 16);
        vgl[0] = r0; vgl[1] = r1; vgl[2] = r2; vgl[3] = r3;
        __syncthreads();
        #pragma unroll
        for (int k = 0; k < 16; k++) Vr[k] = Vs[(g + 18 * k) * 16 + h];
    } else {
        const float* vp = g_votes + colbase * 16;
        #pragma unroll
        for (int k = 0; k < 16; k++) Vr[k] = vp[t + 288 * k];
    }

    // ---- Rw[i] = R[i] * a_[i] ----
    {
        const int i  = t;
        const int Bc = i / 9, uv = i - Bc * 9, u = uv / 3, v = uv - u * 3;
        const float av = act[((b * BCAP + Bc) * WIN + (2 * xw + u)) * WIN + (2 * yw + v)];
        float R;
        if (PHASE == 0) R = 1.0f / 32.0f;
        else            R = g_ap[colbase + i] / (g_denom[b * BKK + i] + EPSV) + EPSV;
        Rw[i] = R * av;
    }
    __syncthreads();

    // ---- mu numerators + sum_R ----
    float accm = 0.f, accr = 0.f;
    #pragma unroll
    for (int k = 0; k < 16; k++) {
        const float rw = Rw[g + 18 * k];
        accm = fmaf(rw, Vr[k], accm);
        accr += rw;
    }
    red[g * 16 + h] = accm;
    if (h == 0) red2[g] = accr;
    __syncthreads();
    float rsum = 0.f;
    if (t < 16) {
        #pragma unroll
        for (int j = 0; j < 18; j++) rsum += red[j * 16 + t];
    }
    if (t == 0) {
        float sr = 0.f;
        #pragma unroll
        for (int j = 0; j < 18; j++) sr += red2[j];
        sumR_s = sr;
    }
    __syncthreads();
    if (t < 16) mu_s[t] = rsum / sumR_s;
    __syncthreads();
    const float mu_h = mu_s[h];

    // ---- sigma^2 ----
    float accs = 0.f;
    #pragma unroll
    for (int k = 0; k < 16; k++) {
        const float d = Vr[k] - mu_h;
        accs = fmaf(Rw[g + 18 * k], d * d, accs);
    }
    red[g * 16 + h] = accs;
    __syncthreads();
    if (t < 16) {
        float ss = 0.f;
        #pragma unroll
        for (int j = 0; j < 18; j++) ss += red[j * 16 + t];
        const float sig = ss / sumR_s;
        logsig_s[t] = __logf(sqrtf(sig) + EPSV);
        inv2s_s[t]  = 0.5f / sig;
    }
    __syncthreads();

    // ---- activation a = sigmoid(lambda * (beta_a - cost)) ----
    if (t == 0) {
        float lsum = 0.f;
        #pragma unroll
        for (int j = 0; j < 16; j++) lsum += logsig_s[j];
        const float cost = sumR_s * (16.f * beta_v[c] + lsum);
        const float z = lam[0] * (beta_a[c] - cost);
        a_s = 1.f / (1.f + __expf(-z));
    }
    __syncthreads();

    if (PHASE == 2) {
        // outputs: mu [b][cww][16] then a [b][cww]
        if (t < 16) out[(size_t)(b * CWW + cww) * 16 + t] = mu_s[t];
        if (t == 0) out[(size_t)NB * CWW * 16 + b * CWW + cww] = a_s;
        return;
    }

    // ---- p-pass: ap[i] = a * sum_h exp(ln_p) ----
    const float inv2s = inv2s_s[h];
    const float lc    = logsig_s[h] + HALF_LN2PI;
    const float an    = a_s;
    #pragma unroll
    for (int k = 0; k < 16; k++) {
        const float d = Vr[k] - mu_h;
        float p = __expf(fmaf(-(d * d), inv2s, -lc));
        // sum across the 16 h-lanes (xor masks < 16 stay inside each half-warp group)
        p += __shfl_xor_sync(0xffffffffu, p, 1);
        p += __shfl_xor_sync(0xffffffffu, p, 2);
        p += __shfl_xor_sync(0xffffffffu, p, 4);
        p += __shfl_xor_sync(0xffffffffu, p, 8);
        if (h == 0) g_ap[colbase + g + 18 * k] = an * p;
    }
}

// denom[b][i] = sum over cww of ap[b][cww][i] — deterministic two-stage reduction
__global__ __launch_bounds__(BKK)
void denom_part_kernel()
{
    const int chunk = blockIdx.x;   // 0..31, 36 cww rows each
    const int b     = blockIdx.y;
    const int i     = threadIdx.x;
    const float* ap = g_ap + (size_t)(b * CWW + chunk * 36) * BKK + i;
    float sv = 0.f;
    #pragma unroll 4
    for (int j = 0; j < 36; j++) sv += ap[(size_t)j * BKK];
    g_part[(b * 32 + chunk) * BKK + i] = sv;
}

__global__ __launch_bounds__(BKK)
void denom_final_kernel()
{
    const int b = blockIdx.x;
    const int i = threadIdx.x;
    float sv = 0.f;
    #pragma unroll
    for (int j = 0; j < 32; j++) sv += g_part[(b * 32 + j) * BKK + i];
    g_denom[b * BKK + i] = sv;
}

extern "C" void kernel_launch(void* const* d_in, const int* in_sizes, int n_in,
                              void* d_out, int out_size)
{
    (void)in_sizes; (void)n_in; (void)out_size;
    const float* poses = (const float*)d_in[0];
    const float* act   = (const float*)d_in[1];
    const float* Wt    = (const float*)d_in[2];
    const float* bv    = (const float*)d_in[3];
    const float* ba    = (const float*)d_in[4];
    const float* lam   = (const float*)d_in[5];
    float* out = (float*)d_out;

    dim3 grid(CWW, NB);
    em_kernel<0><<<grid, BKK>>>(poses, act, Wt, bv, ba, lam, out);
    denom_part_kernel<<<dim3(32, NB), BKK>>>();
    denom_final_kernel<<<NB, BKK>>>();
    em_kernel<1><<<grid, BKK>>>(poses, act, Wt, bv, ba, lam, out);
    denom_part_kernel<<<dim3(32, NB), BKK>>>();
    denom_final_kernel<<<NB, BKK>>>();
    em_kernel<2><<<grid, BKK>>>(poses, act, Wt, bv, ba, lam, out);
}